// round 6
// baseline (speedup 1.0000x reference)
#include <cuda_runtime.h>
#include <cuda_fp16.h>
#include <cstdint>

#define D_IN   128
#define HID    512
#define D_OUTK 128
#define NOBJ   100000
#define NT     200000

#define HB_BYTES  131072           // 128 rows x 512 halfs (1024 B pitch), swizzled
#define STAGE_BYTES 32768          // A 16KB + B 16KB
#define SMEMB (HB_BYTES + 3 * STAGE_BYTES)   // 229376

// Scratch (device globals — no allocation allowed)
__device__ __align__(16) float  g_pooled[(size_t)NOBJ * HID];
__device__ __align__(16) __half g_pooledh[(size_t)NOBJ * HID];
__device__ __align__(16) float  g_counts[NOBJ];
__device__ __align__(16) __half g_objth[(size_t)NOBJ * D_IN];
__device__ __align__(16) __half g_predth[(size_t)NT * D_IN];
// Weights transposed to [n][k], fp16
__device__ __align__(16) __half g_W1T[(size_t)HID * 384];
__device__ __align__(16) __half g_W2T[(size_t)1152 * HID];
__device__ __align__(16) __half g_W3T[(size_t)HID * HID];
__device__ __align__(16) __half g_W4T[(size_t)D_OUTK * HID];

// ---------------------------------------------------------------------------
__device__ __forceinline__ void mma_f16(float* c, const uint32_t* a, const uint32_t* b) {
    asm volatile(
        "mma.sync.aligned.m16n8k16.row.col.f32.f16.f16.f32 "
        "{%0,%1,%2,%3}, {%4,%5,%6,%7}, {%8,%9}, {%0,%1,%2,%3};"
        : "+f"(c[0]), "+f"(c[1]), "+f"(c[2]), "+f"(c[3])
        : "r"(a[0]), "r"(a[1]), "r"(a[2]), "r"(a[3]), "r"(b[0]), "r"(b[1]));
}

__device__ __forceinline__ void cp16(uint32_t d, const void* s, int sz) {
    asm volatile("cp.async.cg.shared.global [%0], [%1], 16, %2;"
                 :: "r"(d), "l"(s), "r"(sz));
}
#define CP_COMMIT() asm volatile("cp.async.commit_group;" ::: "memory")
#define CP_WAIT1()  asm volatile("cp.async.wait_group 1;" ::: "memory")

__device__ __forceinline__ uint32_t lds32(uint32_t addr) {
    uint32_t v;
    asm volatile("ld.shared.b32 %0, [%1];" : "=r"(v) : "r"(addr));
    return v;
}
__device__ __forceinline__ void sts32(uint32_t addr, uint32_t v) {
    asm volatile("st.shared.b32 [%0], %1;" :: "r"(addr), "r"(v));
}

// ---------------------------------------------------------------------------
__global__ void zero_kernel() {
    int i = blockIdx.x * blockDim.x + threadIdx.x;
    float4 z = make_float4(0.f, 0.f, 0.f, 0.f);
    if (i < (NOBJ * HID) / 4) ((float4*)g_pooled)[i] = z;
    if (i < NOBJ / 4)         ((float4*)g_counts)[i] = z;
}

__global__ void count_kernel(const int* __restrict__ edges) {
    int t = blockIdx.x * blockDim.x + threadIdx.x;
    if (t < NT) {
        atomicAdd(&g_counts[edges[2 * t]],     1.f);
        atomicAdd(&g_counts[edges[2 * t + 1]], 1.f);
    }
}

__global__ void cvt_h(const float* __restrict__ src, __half* __restrict__ dst, int n4) {
    int i = blockIdx.x * blockDim.x + threadIdx.x;
    if (i < n4) {
        float4 v = ((const float4*)src)[i];
        __half2* d2 = (__half2*)dst;
        d2[2 * i]     = __floats2half2_rn(v.x, v.y);
        d2[2 * i + 1] = __floats2half2_rn(v.z, v.w);
    }
}

__global__ void cvtT_h(const float* __restrict__ W, __half* __restrict__ WT, int K, int N) {
    int idx = blockIdx.x * blockDim.x + threadIdx.x;
    if (idx < N * K) {
        int n = idx / K, k = idx - n * K;
        WT[idx] = __float2half_rn(W[(size_t)k * N + n]);
    }
}

__global__ void normalize_h() {
    int i = blockIdx.x * blockDim.x + threadIdx.x;
    if (i < (NOBJ * HID) / 4) {
        int r = i >> 7;
        float sc = 1.f / fmaxf(g_counts[r], 1.f);
        float4 v = ((const float4*)g_pooled)[i];
        __half2* d2 = (__half2*)g_pooledh;
        d2[2 * i]     = __floats2half2_rn(v.x * sc, v.y * sc);
        d2[2 * i + 1] = __floats2half2_rn(v.z * sc, v.w * sc);
    }
}

// ---------------------------------------------------------------------------
// PART 0: phase1 h = relu(gather @ W1T + b1) -> hbuf; phase2 GEMM2 w/ scatter
// PART 1: phase1 t = relu(pooledh @ W3T + b3) -> hbuf; phase2 GEMM4 -> out_obj
template<int PART>
__global__ void __launch_bounds__(256, 1) fused(
    const int* __restrict__ edges,
    const float* __restrict__ bias1, const float* __restrict__ bias2,
    float* __restrict__ out, int M)
{
    constexpr int K1  = (PART == 0) ? 384 : 512;
    constexpr int KT1 = K1 / 64;
    constexpr int KT2 = 8;                        // K2 = 512
    constexpr int NCB2 = (PART == 0) ? 9 : 1;

    extern __shared__ __align__(16) char sh[];
    uint32_t sm  = (uint32_t)__cvta_generic_to_shared(sh);
    uint32_t hb  = sm;                            // 128KB
    uint32_t stg = sm + HB_BYTES;                 // 3 x 32KB

    int tid = threadIdx.x, lane = tid & 31, w = tid >> 5;
    int wm = w & 3, wn = w >> 2;                  // 4(m) x 2(n)
    int gr = lane >> 2, ct = lane & 3;
    int row0 = blockIdx.x * 128;

    const __half* Wt1 = (PART == 0) ? g_W1T : g_W3T;
    const __half* Wt2 = (PART == 0) ? g_W2T : g_W4T;

    // =================== phase 1 ===================
    for (int nch = 0; nch < 4; nch++) {
        float acc[2][8][4];
#pragma unroll
        for (int i = 0; i < 2; i++)
#pragma unroll
            for (int j = 0; j < 8; j++)
#pragma unroll
                for (int k = 0; k < 4; k++) acc[i][j][k] = 0.f;

        auto load1 = [&](int kt) {
            int k0 = kt * 64;
            uint32_t ab = stg + (uint32_t)(kt % 3) * STAGE_BYTES;
            uint32_t bb = ab + 16384;
#pragma unroll
            for (int i = 0; i < 4; i++) {
                int f = tid + i * 256;
                int m = f >> 3, ch = f & 7;
                int mg = row0 + m;
                int sz = (mg < M) ? 16 : 0;
                int mc = (mg < M) ? mg : M - 1;
                const char* src;
                if (PART == 0) {
                    int region = k0 >> 7;
                    int bo = (k0 & 127) * 2;
                    if (region == 0)      src = (const char*)(g_objth  + (size_t)edges[2 * mc]     * 128) + bo;
                    else if (region == 1) src = (const char*)(g_predth + (size_t)mc                * 128) + bo;
                    else                  src = (const char*)(g_objth  + (size_t)edges[2 * mc + 1] * 128) + bo;
                } else {
                    src = (const char*)(g_pooledh + (size_t)mc * 512 + k0);
                }
                cp16(ab + (uint32_t)(m * 128 + ((ch ^ (m & 7)) * 16)), src + ch * 16, sz);
            }
#pragma unroll
            for (int i = 0; i < 4; i++) {
                int f = tid + i * 256;
                int n = f >> 3, ch = f & 7;
                const char* src = (const char*)(Wt1 + (size_t)(nch * 128 + n) * K1 + k0) + ch * 16;
                cp16(bb + (uint32_t)(n * 128 + ((ch ^ (n & 7)) * 16)), src, 16);
            }
        };

        load1(0); CP_COMMIT();
        load1(1); CP_COMMIT();

        for (int kt = 0; kt < KT1; kt++) {
            CP_WAIT1();
            __syncthreads();
            if (kt + 2 < KT1) load1(kt + 2);
            CP_COMMIT();
            uint32_t abase = stg + (uint32_t)(kt % 3) * STAGE_BYTES;
            uint32_t bbase = abase + 16384;
#pragma unroll
            for (int kb = 0; kb < 4; kb++) {
                uint32_t c0 = (uint32_t)(((2 * kb)     ^ gr) * 16 + ct * 4);
                uint32_t c1 = (uint32_t)(((2 * kb + 1) ^ gr) * 16 + ct * 4);
                uint32_t a[2][4], bf[8][2];
#pragma unroll
                for (int mf = 0; mf < 2; mf++) {
                    uint32_t r = (uint32_t)(wm * 32 + mf * 16 + gr);
                    a[mf][0] = lds32(abase + r * 128 + c0);
                    a[mf][1] = lds32(abase + (r + 8) * 128 + c0);
                    a[mf][2] = lds32(abase + r * 128 + c1);
                    a[mf][3] = lds32(abase + (r + 8) * 128 + c1);
                }
#pragma unroll
                for (int nf = 0; nf < 8; nf++) {
                    uint32_t n = (uint32_t)(wn * 64 + nf * 8 + gr);
                    bf[nf][0] = lds32(bbase + n * 128 + c0);
                    bf[nf][1] = lds32(bbase + n * 128 + c1);
                }
#pragma unroll
                for (int mf = 0; mf < 2; mf++)
#pragma unroll
                    for (int nf = 0; nf < 8; nf++)
                        mma_f16(acc[mf][nf], a[mf], bf[nf]);
            }
        }

        // epilogue -> hbuf (swizzled 16B chunks on 1024B row pitch)
#pragma unroll
        for (int mf = 0; mf < 2; mf++)
#pragma unroll
            for (int hh = 0; hh < 2; hh++) {
                uint32_t r = (uint32_t)(wm * 32 + mf * 16 + gr + hh * 8);
#pragma unroll
                for (int nf = 0; nf < 8; nf++) {
                    int c = nch * 128 + wn * 64 + nf * 8 + ct * 2;
                    float x = fmaxf(acc[mf][nf][hh * 2 + 0] + bias1[c], 0.f);
                    float y = fmaxf(acc[mf][nf][hh * 2 + 1] + bias1[c + 1], 0.f);
                    uint32_t ch = (uint32_t)(c >> 3);
                    uint32_t sch = (ch & 56u) | ((ch ^ r) & 7u);
                    __half2 hv = __floats2half2_rn(x, y);
                    sts32(hb + r * 1024 + sch * 16 + (uint32_t)ct * 4,
                          *(uint32_t*)&hv);
                }
            }
        __syncthreads();   // staging reuse + hbuf visibility
    }

    // =================== phase 2 ===================
    for (int cb = 0; cb < NCB2; cb++) {
        int colbase = cb * 128;
        int mode, pcol = 0;
        if (PART == 0) {
            if (cb < 4)       { mode = 0; pcol = cb * 128; }
            else if (cb == 4) { mode = 1; }
            else              { mode = 2; pcol = (cb - 5) * 128; }
        } else {
            mode = 3;
        }

        float acc[2][8][4];
#pragma unroll
        for (int i = 0; i < 2; i++)
#pragma unroll
            for (int j = 0; j < 8; j++)
#pragma unroll
                for (int k = 0; k < 4; k++) acc[i][j][k] = 0.f;

        auto load2 = [&](int kt) {
            int k0 = kt * 64;
            uint32_t bb = stg + (uint32_t)(kt % 3) * STAGE_BYTES;
#pragma unroll
            for (int i = 0; i < 4; i++) {
                int f = tid + i * 256;
                int n = f >> 3, ch = f & 7;
                const char* src = (const char*)(Wt2 + (size_t)(colbase + n) * 512 + k0) + ch * 16;
                cp16(bb + (uint32_t)(n * 128 + ((ch ^ (n & 7)) * 16)), src, 16);
            }
        };

        load2(0); CP_COMMIT();
        load2(1); CP_COMMIT();

        for (int kt = 0; kt < KT2; kt++) {
            CP_WAIT1();
            __syncthreads();
            if (kt + 2 < KT2) load2(kt + 2);
            CP_COMMIT();
            uint32_t bbase = stg + (uint32_t)(kt % 3) * STAGE_BYTES;
#pragma unroll
            for (int kb = 0; kb < 4; kb++) {
                int kbg = kt * 4 + kb;
                uint32_t bc0 = (uint32_t)(((2 * kb)     ^ gr) * 16 + ct * 4);
                uint32_t bc1 = (uint32_t)(((2 * kb + 1) ^ gr) * 16 + ct * 4);
                uint32_t a[2][4], bf[8][2];
#pragma unroll
                for (int mf = 0; mf < 2; mf++) {
                    uint32_t r = (uint32_t)(wm * 32 + mf * 16 + gr);
                    uint32_t ch0 = (uint32_t)(2 * kbg), ch1 = ch0 + 1;
                    uint32_t s0 = (ch0 & 56u) | ((ch0 ^ r) & 7u);
                    uint32_t s1 = (ch1 & 56u) | ((ch1 ^ r) & 7u);
                    a[mf][0] = lds32(hb + r * 1024 + s0 * 16 + (uint32_t)ct * 4);
                    a[mf][1] = lds32(hb + (r + 8) * 1024 + s0 * 16 + (uint32_t)ct * 4);
                    a[mf][2] = lds32(hb + r * 1024 + s1 * 16 + (uint32_t)ct * 4);
                    a[mf][3] = lds32(hb + (r + 8) * 1024 + s1 * 16 + (uint32_t)ct * 4);
                }
#pragma unroll
                for (int nf = 0; nf < 8; nf++) {
                    uint32_t n = (uint32_t)(wn * 64 + nf * 8 + gr);
                    bf[nf][0] = lds32(bbase + n * 128 + bc0);
                    bf[nf][1] = lds32(bbase + n * 128 + bc1);
                }
#pragma unroll
                for (int mf = 0; mf < 2; mf++)
#pragma unroll
                    for (int nf = 0; nf < 8; nf++)
                        mma_f16(acc[mf][nf], a[mf], bf[nf]);
            }
        }

        // ---- global epilogue ----
#pragma unroll
        for (int mf = 0; mf < 2; mf++)
#pragma unroll
            for (int hh = 0; hh < 2; hh++) {
                int r = row0 + wm * 32 + mf * 16 + gr + hh * 8;
                if (r >= M) continue;
                int lc = wn * 64 + ct * 2;
                if (mode == 0 || mode == 2) {
                    int sidx = (mode == 0) ? edges[2 * r] : edges[2 * r + 1];
                    float* dst = g_pooled + (size_t)sidx * HID + pcol + lc;
#pragma unroll
                    for (int nf = 0; nf < 8; nf++) {
                        int c = colbase + lc + nf * 8;
                        atomicAdd(dst + nf * 8,
                                  fmaxf(acc[mf][nf][hh * 2 + 0] + bias2[c], 0.f));
                        atomicAdd(dst + nf * 8 + 1,
                                  fmaxf(acc[mf][nf][hh * 2 + 1] + bias2[c + 1], 0.f));
                    }
                } else {
                    float* dst = out + (size_t)r * D_OUTK + lc;
#pragma unroll
                    for (int nf = 0; nf < 8; nf++) {
                        int c = colbase + lc + nf * 8;
                        float2 o;
                        o.x = fmaxf(acc[mf][nf][hh * 2 + 0] + bias2[c], 0.f);
                        o.y = fmaxf(acc[mf][nf][hh * 2 + 1] + bias2[c + 1], 0.f);
                        *(float2*)(dst + nf * 8) = o;
                    }
                }
            }
        __syncthreads();   // staging reuse across col blocks
    }
}

// ---------------------------------------------------------------------------
extern "C" void kernel_launch(void* const* d_in, const int* in_sizes, int n_in,
                              void* d_out, int out_size)
{
    const float* obj   = (const float*)d_in[0];
    const float* pred  = (const float*)d_in[1];
    const int*   edges = (const int*)  d_in[2];
    const float* W1 = (const float*)d_in[3];
    const float* b1 = (const float*)d_in[4];
    const float* W2 = (const float*)d_in[5];
    const float* b2 = (const float*)d_in[6];
    const float* W3 = (const float*)d_in[7];
    const float* b3 = (const float*)d_in[8];
    const float* W4 = (const float*)d_in[9];
    const float* b4 = (const float*)d_in[10];

    float* out     = (float*)d_out;
    float* out_obj = out;                           // (NOBJ, 128)
    float* out_p   = out + (size_t)NOBJ * D_OUTK;   // (NT, 128)

    cudaFuncSetAttribute(fused<0>, cudaFuncAttributeMaxDynamicSharedMemorySize, SMEMB);
    cudaFuncSetAttribute(fused<1>, cudaFuncAttributeMaxDynamicSharedMemorySize, SMEMB);

    __half *p_objth, *p_predth, *p_W1T, *p_W2T, *p_W3T, *p_W4T;
    cudaGetSymbolAddress((void**)&p_objth,  g_objth);
    cudaGetSymbolAddress((void**)&p_predth, g_predth);
    cudaGetSymbolAddress((void**)&p_W1T,    g_W1T);
    cudaGetSymbolAddress((void**)&p_W2T,    g_W2T);
    cudaGetSymbolAddress((void**)&p_W3T,    g_W3T);
    cudaGetSymbolAddress((void**)&p_W4T,    g_W4T);

    zero_kernel<<<(NOBJ * HID / 4 + 255) / 256, 256>>>();
    count_kernel<<<(NT + 255) / 256, 256>>>(edges);

    {
        int n4 = NOBJ * D_IN / 4;
        cvt_h<<<(n4 + 255) / 256, 256>>>(obj, p_objth, n4);
    }
    {
        int n4 = NT * D_IN / 4;
        cvt_h<<<(n4 + 255) / 256, 256>>>(pred, p_predth, n4);
    }
    auto cvtT = [](const float* s, __half* d, int K, int N) {
        int n = K * N;
        cvtT_h<<<(n + 255) / 256, 256>>>(s, d, K, N);
    };
    cvtT(W1, p_W1T, 384, 512);
    cvtT(W2, p_W2T, 512, 1152);
    cvtT(W3, p_W3T, 512, 512);
    cvtT(W4, p_W4T, 512, 128);

    int gx_t = (NT + 127) / 128;    // 1563
    int gx_o = (NOBJ + 127) / 128;  // 782

    fused<0><<<gx_t, 256, SMEMB>>>(edges, b1, b2, out_p, NT);
    normalize_h<<<(NOBJ * HID / 4 + 255) / 256, 256>>>();
    fused<1><<<gx_o, 256, SMEMB>>>(edges, b3, b4, out_obj, NOBJ);
}

// round 7
// speedup vs baseline: 1.2923x; 1.2923x over previous
#include <cuda_runtime.h>
#include <cuda_fp16.h>
#include <cstdint>

#define D_IN   128
#define HID    512
#define D_OUTK 128
#define NOBJ   100000
#define NT     200000

#define BM 128
#define BN 128
#define BK 64                      // halfs per stage-chunk (128 B per row)
#define A_BYTES (BM * BK * 2)      // 16 KB
#define STAGE_BYTES (2 * A_BYTES)  // A + B = 32 KB
#define NSTAGE 3
#define SMEMB (NSTAGE * STAGE_BYTES)

// Scratch (device globals — no allocation allowed)
__device__ __align__(16) __half g_h[(size_t)NT * HID];
__device__ __align__(16) float  g_pooled[(size_t)NOBJ * HID];
__device__ __align__(16) __half g_pooledh[(size_t)NOBJ * HID];
__device__ __align__(16) __half g_tmph[(size_t)NOBJ * HID];
__device__ __align__(16) float  g_counts[NOBJ];
__device__ __align__(16) __half g_objth[(size_t)NOBJ * D_IN];
__device__ __align__(16) __half g_predth[(size_t)NT * D_IN];
// Weights transposed to [n][k], fp16
__device__ __align__(16) __half g_W1T[(size_t)HID * 384];
__device__ __align__(16) __half g_W2T[(size_t)1152 * HID];
__device__ __align__(16) __half g_W3T[(size_t)HID * HID];
__device__ __align__(16) __half g_W4T[(size_t)D_OUTK * HID];

// ---------------------------------------------------------------------------
__device__ __forceinline__ void mma_f16(float* c, const uint32_t* a, const uint32_t* b) {
    asm volatile(
        "mma.sync.aligned.m16n8k16.row.col.f32.f16.f16.f32 "
        "{%0,%1,%2,%3}, {%4,%5,%6,%7}, {%8,%9}, {%0,%1,%2,%3};"
        : "+f"(c[0]), "+f"(c[1]), "+f"(c[2]), "+f"(c[3])
        : "r"(a[0]), "r"(a[1]), "r"(a[2]), "r"(a[3]), "r"(b[0]), "r"(b[1]));
}

__device__ __forceinline__ void ldsm4(uint32_t& r0, uint32_t& r1, uint32_t& r2,
                                      uint32_t& r3, uint32_t addr) {
    asm volatile("ldmatrix.sync.aligned.m8n8.x4.shared.b16 {%0,%1,%2,%3}, [%4];"
                 : "=r"(r0), "=r"(r1), "=r"(r2), "=r"(r3) : "r"(addr));
}

__device__ __forceinline__ void cp16(uint32_t d, const void* s, int sz) {
    asm volatile("cp.async.cg.shared.global [%0], [%1], 16, %2;"
                 :: "r"(d), "l"(s), "r"(sz));
}
#define CP_COMMIT() asm volatile("cp.async.commit_group;" ::: "memory")
#define CP_WAIT1()  asm volatile("cp.async.wait_group 1;" ::: "memory")

// ---------------------------------------------------------------------------
__global__ void zero_kernel() {
    int i = blockIdx.x * blockDim.x + threadIdx.x;
    float4 z = make_float4(0.f, 0.f, 0.f, 0.f);
    if (i < (NOBJ * HID) / 4) ((float4*)g_pooled)[i] = z;
    if (i < NOBJ / 4)         ((float4*)g_counts)[i] = z;
}

__global__ void count_kernel(const int* __restrict__ edges) {
    int t = blockIdx.x * blockDim.x + threadIdx.x;
    if (t < NT) {
        atomicAdd(&g_counts[edges[2 * t]],     1.f);
        atomicAdd(&g_counts[edges[2 * t + 1]], 1.f);
    }
}

__global__ void cvt_h(const float* __restrict__ src, __half* __restrict__ dst, int n4) {
    int i = blockIdx.x * blockDim.x + threadIdx.x;
    if (i < n4) {
        float4 v = ((const float4*)src)[i];
        __half2* d2 = (__half2*)dst;
        d2[2 * i]     = __floats2half2_rn(v.x, v.y);
        d2[2 * i + 1] = __floats2half2_rn(v.z, v.w);
    }
}

// WT[n][k] = half(W[k][n])
__global__ void cvtT_h(const float* __restrict__ W, __half* __restrict__ WT, int K, int N) {
    int idx = blockIdx.x * blockDim.x + threadIdx.x;
    if (idx < N * K) {
        int n = idx / K, k = idx - n * K;
        WT[idx] = __float2half_rn(W[(size_t)k * N + n]);
    }
}

// pooledh[r][c] = half(pooled[r][c] / max(counts[r],1))
__global__ void normalize_h() {
    int i = blockIdx.x * blockDim.x + threadIdx.x;
    if (i < (NOBJ * HID) / 4) {
        int r = i >> 7;
        float sc = 1.f / fmaxf(g_counts[r], 1.f);
        float4 v = ((const float4*)g_pooled)[i];
        __half2* d2 = (__half2*)g_pooledh;
        d2[2 * i]     = __floats2half2_rn(v.x * sc, v.y * sc);
        d2[2 * i + 1] = __floats2half2_rn(v.z * sc, v.w * sc);
    }
}

// ---------------------------------------------------------------------------
// KIND 0: g_h    = h(relu(gather @ W1T + b1))        M=NT,   K=384, N=512
// KIND 1: scatter/out_p from relu(g_h @ W2T + b2)    M=NT,   K=512, N=1152
// KIND 2: g_tmph = h(relu(pooledh @ W3T + b3))       M=NOBJ, K=512, N=512
// KIND 3: out_obj = relu(g_tmph @ W4T + b4)          M=NOBJ, K=512, N=128
template<int KIND>
__global__ void __launch_bounds__(256, 2) hgemm(const int* __restrict__ edges,
                                                const float* __restrict__ bias,
                                                float* __restrict__ out, int M)
{
    constexpr int K  = (KIND == 0) ? 384 : 512;
    constexpr int KT = K / BK;
    extern __shared__ __align__(16) char sh[];
    uint32_t sm = (uint32_t)__cvta_generic_to_shared(sh);

    int tid = threadIdx.x, lane = tid & 31, w = tid >> 5;
    int wm = w & 3, wn = w >> 2;                 // 4 (m) x 2 (n) warps
    int gr = lane >> 2, ct = lane & 3;
    int sel = lane >> 3, lr = lane & 7;          // ldmatrix lane roles
    int row0 = blockIdx.x >= 0 ? blockIdx.y * BM : 0;
    int col0 = blockIdx.x * BN;

    int mode = 0, pcol = 0;                      // KIND 1 column routing
    if (KIND == 1) {
        int bx = blockIdx.x;
        if (bx < 4)       { mode = 0; pcol = bx * 128; }
        else if (bx == 4) { mode = 1; pcol = 0; }
        else              { mode = 2; pcol = (bx - 5) * 128; }
    }

    const __half* Wt   = (KIND == 0) ? g_W1T : (KIND == 1) ? g_W2T
                       : (KIND == 2) ? g_W3T : g_W4T;
    const __half* Amat = (KIND == 1) ? g_h : (KIND == 2) ? g_pooledh : g_tmph;

    float acc[2][8][4];
#pragma unroll
    for (int i = 0; i < 2; i++)
#pragma unroll
        for (int j = 0; j < 8; j++)
#pragma unroll
            for (int k = 0; k < 4; k++) acc[i][j][k] = 0.f;

    auto load_stage = [&](int kt) {
        int k0 = kt * BK;                          // in halfs
        uint32_t ab = sm + (uint32_t)(kt % NSTAGE) * STAGE_BYTES;
        uint32_t bb = ab + A_BYTES;
#pragma unroll
        for (int i = 0; i < 4; i++) {              // A: 128 rows x 8 chunks
            int f = tid + i * 256;
            int m = f >> 3, ch = f & 7;
            int mg = row0 + m;
            int sz = (mg < M) ? 16 : 0;
            int mc = (mg < M) ? mg : M - 1;
            const char* src;
            if (KIND == 0) {
                int region = k0 >> 7;
                int bo = (k0 & 127) * 2;
                if (region == 0)      src = (const char*)(g_objth  + (size_t)edges[2 * mc]     * 128) + bo;
                else if (region == 1) src = (const char*)(g_predth + (size_t)mc                * 128) + bo;
                else                  src = (const char*)(g_objth  + (size_t)edges[2 * mc + 1] * 128) + bo;
            } else {
                src = (const char*)(Amat + (size_t)mc * K + k0);
            }
            cp16(ab + (uint32_t)(m * 128 + ((ch ^ (m & 7)) * 16)), src + ch * 16, sz);
        }
#pragma unroll
        for (int i = 0; i < 4; i++) {              // B: 128 n-rows x 8 chunks
            int f = tid + i * 256;
            int n = f >> 3, ch = f & 7;
            const char* src = (const char*)(Wt + (size_t)(col0 + n) * K + k0) + ch * 16;
            cp16(bb + (uint32_t)(n * 128 + ((ch ^ (n & 7)) * 16)), src, 16);
        }
    };

    // Per-lane ldmatrix row bases (stage-relative byte offsets, swizzle applied per-chunk)
    // A matrices: sel0:(R+lr, c0) sel1:(R+8+lr, c0) sel2:(R+lr, c1) sel3:(R+8+lr, c1)
    int a_row[2];
#pragma unroll
    for (int mf = 0; mf < 2; mf++)
        a_row[mf] = wm * 32 + mf * 16 + lr + ((sel & 1) << 3);
    // B matrices for pair p: sel0:(n0+lr, c0) sel1:(n0+lr, c1) sel2:(n0+8+lr, c0) sel3:(n0+8+lr, c1)
    int b_row[4];
#pragma unroll
    for (int p = 0; p < 4; p++)
        b_row[p] = wn * 64 + p * 16 + lr + ((sel >> 1) << 3);

    auto mma_stage = [&](int b) {
        uint32_t abase = sm + (uint32_t)b * STAGE_BYTES;
        uint32_t bbase = abase + A_BYTES;
#pragma unroll
        for (int kb = 0; kb < BK / 16; kb++) {
            uint32_t a[2][4], bf[8][2];
            int a_ch = 2 * kb + (sel >> 1);
#pragma unroll
            for (int mf = 0; mf < 2; mf++) {
                int r = a_row[mf];
                uint32_t addr = abase + (uint32_t)(r * 128 + ((a_ch ^ (r & 7)) * 16));
                ldsm4(a[mf][0], a[mf][1], a[mf][2], a[mf][3], addr);
            }
            int b_ch = 2 * kb + (sel & 1);
#pragma unroll
            for (int p = 0; p < 4; p++) {
                int r = b_row[p];
                uint32_t addr = bbase + (uint32_t)(r * 128 + ((b_ch ^ (r & 7)) * 16));
                ldsm4(bf[2 * p][0], bf[2 * p][1], bf[2 * p + 1][0], bf[2 * p + 1][1], addr);
            }
#pragma unroll
            for (int mf = 0; mf < 2; mf++)
#pragma unroll
                for (int nf = 0; nf < 8; nf++)
                    mma_f16(acc[mf][nf], a[mf], bf[nf]);
        }
    };

    load_stage(0); CP_COMMIT();
    load_stage(1); CP_COMMIT();

    for (int kt = 0; kt < KT; kt++) {
        CP_WAIT1();
        __syncthreads();
        if (kt + 2 < KT) load_stage(kt + 2);
        CP_COMMIT();
        mma_stage(kt % NSTAGE);
    }

    // ---- epilogue ----
    float bb[8][2];
#pragma unroll
    for (int nf = 0; nf < 8; nf++) {
        int c = col0 + wn * 64 + nf * 8 + ct * 2;
        bb[nf][0] = bias[c]; bb[nf][1] = bias[c + 1];
    }

#pragma unroll
    for (int mf = 0; mf < 2; mf++)
#pragma unroll
        for (int half = 0; half < 2; half++) {
            int r = row0 + wm * 32 + mf * 16 + gr + half * 8;
            if (r >= M) continue;
            int cbase = wn * 64 + ct * 2;
            if (KIND == 0 || KIND == 2) {
                __half* dst = ((KIND == 0) ? g_h : g_tmph) + (size_t)r * HID + col0 + cbase;
#pragma unroll
                for (int nf = 0; nf < 8; nf++) {
                    float x = fmaxf(acc[mf][nf][half * 2 + 0] + bb[nf][0], 0.f);
                    float y = fmaxf(acc[mf][nf][half * 2 + 1] + bb[nf][1], 0.f);
                    *(__half2*)(dst + nf * 8) = __floats2half2_rn(x, y);
                }
            } else if (KIND == 3) {
                float* dst = out + (size_t)r * D_OUTK + cbase;
#pragma unroll
                for (int nf = 0; nf < 8; nf++) {
                    float2 o;
                    o.x = fmaxf(acc[mf][nf][half * 2 + 0] + bb[nf][0], 0.f);
                    o.y = fmaxf(acc[mf][nf][half * 2 + 1] + bb[nf][1], 0.f);
                    *(float2*)(dst + nf * 8) = o;
                }
            } else {  // KIND == 1
                if (mode == 1) {
                    float* dst = out + (size_t)r * D_OUTK + cbase;
#pragma unroll
                    for (int nf = 0; nf < 8; nf++) {
                        float2 o;
                        o.x = fmaxf(acc[mf][nf][half * 2 + 0] + bb[nf][0], 0.f);
                        o.y = fmaxf(acc[mf][nf][half * 2 + 1] + bb[nf][1], 0.f);
                        *(float2*)(dst + nf * 8) = o;
                    }
                } else {
                    int sidx = (mode == 0) ? edges[2 * r] : edges[2 * r + 1];
                    float* dst = g_pooled + (size_t)sidx * HID + pcol + cbase;
#pragma unroll
                    for (int nf = 0; nf < 8; nf++) {
                        atomicAdd(dst + nf * 8,
                                  fmaxf(acc[mf][nf][half * 2 + 0] + bb[nf][0], 0.f));
                        atomicAdd(dst + nf * 8 + 1,
                                  fmaxf(acc[mf][nf][half * 2 + 1] + bb[nf][1], 0.f));
                    }
                }
            }
        }
}

// ---------------------------------------------------------------------------
extern "C" void kernel_launch(void* const* d_in, const int* in_sizes, int n_in,
                              void* d_out, int out_size)
{
    const float* obj   = (const float*)d_in[0];
    const float* pred  = (const float*)d_in[1];
    const int*   edges = (const int*)  d_in[2];
    const float* W1 = (const float*)d_in[3];
    const float* b1 = (const float*)d_in[4];
    const float* W2 = (const float*)d_in[5];
    const float* b2 = (const float*)d_in[6];
    const float* W3 = (const float*)d_in[7];
    const float* b3 = (const float*)d_in[8];
    const float* W4 = (const float*)d_in[9];
    const float* b4 = (const float*)d_in[10];

    float* out     = (float*)d_out;
    float* out_obj = out;                           // (NOBJ, 128)
    float* out_p   = out + (size_t)NOBJ * D_OUTK;   // (NT, 128)

    cudaFuncSetAttribute(hgemm<0>, cudaFuncAttributeMaxDynamicSharedMemorySize, SMEMB);
    cudaFuncSetAttribute(hgemm<1>, cudaFuncAttributeMaxDynamicSharedMemorySize, SMEMB);
    cudaFuncSetAttribute(hgemm<2>, cudaFuncAttributeMaxDynamicSharedMemorySize, SMEMB);
    cudaFuncSetAttribute(hgemm<3>, cudaFuncAttributeMaxDynamicSharedMemorySize, SMEMB);

    __half *p_objth, *p_predth, *p_W1T, *p_W2T, *p_W3T, *p_W4T;
    cudaGetSymbolAddress((void**)&p_objth,  g_objth);
    cudaGetSymbolAddress((void**)&p_predth, g_predth);
    cudaGetSymbolAddress((void**)&p_W1T,    g_W1T);
    cudaGetSymbolAddress((void**)&p_W2T,    g_W2T);
    cudaGetSymbolAddress((void**)&p_W3T,    g_W3T);
    cudaGetSymbolAddress((void**)&p_W4T,    g_W4T);

    zero_kernel<<<(NOBJ * HID / 4 + 255) / 256, 256>>>();
    count_kernel<<<(NT + 255) / 256, 256>>>(edges);

    {
        int n4 = NOBJ * D_IN / 4;
        cvt_h<<<(n4 + 255) / 256, 256>>>(obj, p_objth, n4);
    }
    {
        int n4 = NT * D_IN / 4;
        cvt_h<<<(n4 + 255) / 256, 256>>>(pred, p_predth, n4);
    }
    auto cvtT = [](const float* s, __half* d, int K, int N) {
        int n = K * N;
        cvtT_h<<<(n + 255) / 256, 256>>>(s, d, K, N);
    };
    cvtT(W1, p_W1T, 384, 512);
    cvtT(W2, p_W2T, 512, 1152);
    cvtT(W3, p_W3T, 512, 512);
    cvtT(W4, p_W4T, 512, 128);

    int gy_t = (NT + BM - 1) / BM;    // 1563
    int gy_o = (NOBJ + BM - 1) / BM;  // 782

    hgemm<0><<<dim3(4, gy_t), 256, SMEMB>>>(edges, b1, nullptr, NT);
    hgemm<1><<<dim3(9, gy_t), 256, SMEMB>>>(edges, b2, out_p, NT);
    normalize_h<<<(NOBJ * HID / 4 + 255) / 256, 256>>>();
    hgemm<2><<<dim3(4, gy_o), 256, SMEMB>>>(edges, b3, nullptr, NOBJ);
    hgemm<3><<<dim3(1, gy_o), 256, SMEMB>>>(edges, b4, out_obj, NOBJ);
}

// round 8
// speedup vs baseline: 1.3560x; 1.0493x over previous
#include <cuda_runtime.h>
#include <cuda_fp16.h>
#include <cstdint>

#define D_IN   128
#define HID    512
#define D_OUTK 128
#define NOBJ   100000
#define NT     200000

#define BM 128
#define BN 128
#define BK 64                      // halfs per stage-chunk (128 B per row)
#define A_BYTES (BM * BK * 2)      // 16 KB
#define STAGE_BYTES (2 * A_BYTES)  // A + B = 32 KB
#define NSTAGE 3
#define SMEMB (NSTAGE * STAGE_BYTES)

// Scratch (device globals — no allocation allowed)
__device__ __align__(16) __half g_h[(size_t)NT * HID];
__device__ __align__(16) float  g_pooled[(size_t)NOBJ * HID];
__device__ __align__(16) __half g_pooledh[(size_t)NOBJ * HID];
__device__ __align__(16) __half g_tmph[(size_t)NOBJ * HID];
__device__ __align__(16) float  g_counts[NOBJ];
__device__ __align__(16) __half g_objth[(size_t)NOBJ * D_IN];
__device__ __align__(16) __half g_predth[(size_t)NT * D_IN];
// Weights transposed to [n][k], fp16
__device__ __align__(16) __half g_W1T[(size_t)HID * 384];
__device__ __align__(16) __half g_W2T[(size_t)1152 * HID];
__device__ __align__(16) __half g_W3T[(size_t)HID * HID];
__device__ __align__(16) __half g_W4T[(size_t)D_OUTK * HID];

// ---------------------------------------------------------------------------
__device__ __forceinline__ void mma_f16(float* c, const uint32_t* a, const uint32_t* b) {
    asm volatile(
        "mma.sync.aligned.m16n8k16.row.col.f32.f16.f16.f32 "
        "{%0,%1,%2,%3}, {%4,%5,%6,%7}, {%8,%9}, {%0,%1,%2,%3};"
        : "+f"(c[0]), "+f"(c[1]), "+f"(c[2]), "+f"(c[3])
        : "r"(a[0]), "r"(a[1]), "r"(a[2]), "r"(a[3]), "r"(b[0]), "r"(b[1]));
}

__device__ __forceinline__ void ldsm4(uint32_t& r0, uint32_t& r1, uint32_t& r2,
                                      uint32_t& r3, uint32_t addr) {
    asm volatile("ldmatrix.sync.aligned.m8n8.x4.shared.b16 {%0,%1,%2,%3}, [%4];"
                 : "=r"(r0), "=r"(r1), "=r"(r2), "=r"(r3) : "r"(addr));
}

__device__ __forceinline__ void cp16(uint32_t d, const void* s, int sz) {
    asm volatile("cp.async.cg.shared.global [%0], [%1], 16, %2;"
                 :: "r"(d), "l"(s), "r"(sz));
}
#define CP_COMMIT() asm volatile("cp.async.commit_group;" ::: "memory")
#define CP_WAIT1()  asm volatile("cp.async.wait_group 1;" ::: "memory")

__device__ __forceinline__ void red_add_v2(float* addr, float x, float y) {
    asm volatile("red.global.add.v2.f32 [%0], {%1, %2};"
                 :: "l"(addr), "f"(x), "f"(y) : "memory");
}

// ---------------------------------------------------------------------------
__global__ void zero_counts() {
    int i = blockIdx.x * blockDim.x + threadIdx.x;
    if (i < NOBJ) g_counts[i] = 0.f;
}

// Section-dispatched prep: pooled zero | cvt obj | cvt pred | cvtT W1-4 | count
#define NB_POOL  50000   // NOBJ*HID/4 float4 / 256
#define NB_OBJ   12500   // NOBJ*128/4 / 256
#define NB_PRED  25000   // NT*128/4 / 256
#define NB_W1    768     // 384*512/256
#define NB_W2    2304    // 512*1152/256
#define NB_W3    1024    // 512*512/256
#define NB_W4    256     // 512*128/256
#define NB_CNT   782     // ceil(NT/256)
#define NB_TOTAL (NB_POOL + NB_OBJ + NB_PRED + NB_W1 + NB_W2 + NB_W3 + NB_W4 + NB_CNT)

__device__ __forceinline__ void cvt_sec(const float* src, __half* dst, int i) {
    float4 v = ((const float4*)src)[i];
    __half2* d2 = (__half2*)dst;
    d2[2 * i]     = __floats2half2_rn(v.x, v.y);
    d2[2 * i + 1] = __floats2half2_rn(v.z, v.w);
}
__device__ __forceinline__ void cvtT_sec(const float* W, __half* WT, int K, int N, int idx) {
    int n = idx / K, k = idx - n * K;
    WT[idx] = __float2half_rn(W[(size_t)k * N + n]);
}

__global__ void prep_kernel(const float* __restrict__ obj, const float* __restrict__ pred,
                            const int* __restrict__ edges,
                            const float* __restrict__ W1, const float* __restrict__ W2,
                            const float* __restrict__ W3, const float* __restrict__ W4)
{
    int b = blockIdx.x;
    int t = threadIdx.x;
    if (b < NB_POOL) {
        int i = b * 256 + t;
        ((float4*)g_pooled)[i] = make_float4(0.f, 0.f, 0.f, 0.f);
        return;
    }
    b -= NB_POOL;
    if (b < NB_OBJ)  { cvt_sec(obj,  g_objth,  b * 256 + t); return; }
    b -= NB_OBJ;
    if (b < NB_PRED) { cvt_sec(pred, g_predth, b * 256 + t); return; }
    b -= NB_PRED;
    if (b < NB_W1) { cvtT_sec(W1, g_W1T, 384, 512,  b * 256 + t); return; }
    b -= NB_W1;
    if (b < NB_W2) { cvtT_sec(W2, g_W2T, 512, 1152, b * 256 + t); return; }
    b -= NB_W2;
    if (b < NB_W3) { cvtT_sec(W3, g_W3T, 512, 512,  b * 256 + t); return; }
    b -= NB_W3;
    if (b < NB_W4) { cvtT_sec(W4, g_W4T, 512, 128,  b * 256 + t); return; }
    b -= NB_W4;
    {
        int e = b * 256 + t;
        if (e < NT) {
            atomicAdd(&g_counts[edges[2 * e]],     1.f);
            atomicAdd(&g_counts[edges[2 * e + 1]], 1.f);
        }
    }
}

// pooledh[r][c] = half(pooled[r][c] / max(counts[r],1))
__global__ void normalize_h() {
    int i = blockIdx.x * blockDim.x + threadIdx.x;
    if (i < (NOBJ * HID) / 4) {
        int r = i >> 7;
        float sc = 1.f / fmaxf(g_counts[r], 1.f);
        float4 v = ((const float4*)g_pooled)[i];
        __half2* d2 = (__half2*)g_pooledh;
        d2[2 * i]     = __floats2half2_rn(v.x * sc, v.y * sc);
        d2[2 * i + 1] = __floats2half2_rn(v.z * sc, v.w * sc);
    }
}

// ---------------------------------------------------------------------------
// KIND 0: g_h    = h(relu(gather @ W1T + b1))        M=NT,   K=384, N=512
// KIND 1: scatter/out_p from relu(g_h @ W2T + b2)    M=NT,   K=512, N=1152
// KIND 2: g_tmph = h(relu(pooledh @ W3T + b3))       M=NOBJ, K=512, N=512
// KIND 3: out_obj = relu(g_tmph @ W4T + b4)          M=NOBJ, K=512, N=128
template<int KIND>
__global__ void __launch_bounds__(256, 2) hgemm(const int* __restrict__ edges,
                                                const float* __restrict__ bias,
                                                float* __restrict__ out, int M)
{
    constexpr int K  = (KIND == 0) ? 384 : 512;
    constexpr int KT = K / BK;
    extern __shared__ __align__(16) char sh[];
    uint32_t sm = (uint32_t)__cvta_generic_to_shared(sh);

    int tid = threadIdx.x, lane = tid & 31, w = tid >> 5;
    int wm = w & 3, wn = w >> 2;                 // 4 (m) x 2 (n) warps
    int gr = lane >> 2, ct = lane & 3;
    int sel = lane >> 3, lr = lane & 7;          // ldmatrix lane roles
    int row0 = blockIdx.y * BM;
    int col0 = blockIdx.x * BN;

    int mode = 0, pcol = 0;                      // KIND 1 column routing
    if (KIND == 1) {
        int bx = blockIdx.x;
        if (bx < 4)       { mode = 0; pcol = bx * 128; }
        else if (bx == 4) { mode = 1; pcol = 0; }
        else              { mode = 2; pcol = (bx - 5) * 128; }
    }

    const __half* Wt   = (KIND == 0) ? g_W1T : (KIND == 1) ? g_W2T
                       : (KIND == 2) ? g_W3T : g_W4T;
    const __half* Amat = (KIND == 1) ? g_h : (KIND == 2) ? g_pooledh : g_tmph;

    float acc[2][8][4];
#pragma unroll
    for (int i = 0; i < 2; i++)
#pragma unroll
        for (int j = 0; j < 8; j++)
#pragma unroll
            for (int k = 0; k < 4; k++) acc[i][j][k] = 0.f;

    auto load_stage = [&](int kt) {
        int k0 = kt * BK;                          // in halfs
        uint32_t ab = sm + (uint32_t)(kt % NSTAGE) * STAGE_BYTES;
        uint32_t bb = ab + A_BYTES;
#pragma unroll
        for (int i = 0; i < 4; i++) {              // A: 128 rows x 8 chunks
            int f = tid + i * 256;
            int m = f >> 3, ch = f & 7;
            int mg = row0 + m;
            int sz = (mg < M) ? 16 : 0;
            int mc = (mg < M) ? mg : M - 1;
            const char* src;
            if (KIND == 0) {
                int region = k0 >> 7;
                int bo = (k0 & 127) * 2;
                if (region == 0)      src = (const char*)(g_objth  + (size_t)edges[2 * mc]     * 128) + bo;
                else if (region == 1) src = (const char*)(g_predth + (size_t)mc                * 128) + bo;
                else                  src = (const char*)(g_objth  + (size_t)edges[2 * mc + 1] * 128) + bo;
            } else {
                src = (const char*)(Amat + (size_t)mc * K + k0);
            }
            cp16(ab + (uint32_t)(m * 128 + ((ch ^ (m & 7)) * 16)), src + ch * 16, sz);
        }
#pragma unroll
        for (int i = 0; i < 4; i++) {              // B: 128 n-rows x 8 chunks
            int f = tid + i * 256;
            int n = f >> 3, ch = f & 7;
            const char* src = (const char*)(Wt + (size_t)(col0 + n) * K + k0) + ch * 16;
            cp16(bb + (uint32_t)(n * 128 + ((ch ^ (n & 7)) * 16)), src, 16);
        }
    };

    int a_row[2];
#pragma unroll
    for (int mf = 0; mf < 2; mf++)
        a_row[mf] = wm * 32 + mf * 16 + lr + ((sel & 1) << 3);
    int b_row[4];
#pragma unroll
    for (int p = 0; p < 4; p++)
        b_row[p] = wn * 64 + p * 16 + lr + ((sel >> 1) << 3);

    auto mma_stage = [&](int b) {
        uint32_t abase = sm + (uint32_t)b * STAGE_BYTES;
        uint32_t bbase = abase + A_BYTES;
#pragma unroll
        for (int kb = 0; kb < BK / 16; kb++) {
            uint32_t a[2][4], bf[8][2];
            int a_ch = 2 * kb + (sel >> 1);
#pragma unroll
            for (int mf = 0; mf < 2; mf++) {
                int r = a_row[mf];
                uint32_t addr = abase + (uint32_t)(r * 128 + ((a_ch ^ (r & 7)) * 16));
                ldsm4(a[mf][0], a[mf][1], a[mf][2], a[mf][3], addr);
            }
            int b_ch = 2 * kb + (sel & 1);
#pragma unroll
            for (int p = 0; p < 4; p++) {
                int r = b_row[p];
                uint32_t addr = bbase + (uint32_t)(r * 128 + ((b_ch ^ (r & 7)) * 16));
                ldsm4(bf[2 * p][0], bf[2 * p][1], bf[2 * p + 1][0], bf[2 * p + 1][1], addr);
            }
#pragma unroll
            for (int mf = 0; mf < 2; mf++)
#pragma unroll
                for (int nf = 0; nf < 8; nf++)
                    mma_f16(acc[mf][nf], a[mf], bf[nf]);
        }
    };

    load_stage(0); CP_COMMIT();
    load_stage(1); CP_COMMIT();

    for (int kt = 0; kt < KT; kt++) {
        CP_WAIT1();
        __syncthreads();
        if (kt + 2 < KT) load_stage(kt + 2);
        CP_COMMIT();
        mma_stage(kt % NSTAGE);
    }

    // ---- epilogue ----
    float bb[8][2];
#pragma unroll
    for (int nf = 0; nf < 8; nf++) {
        int c = col0 + wn * 64 + nf * 8 + ct * 2;
        bb[nf][0] = bias[c]; bb[nf][1] = bias[c + 1];
    }

#pragma unroll
    for (int mf = 0; mf < 2; mf++)
#pragma unroll
        for (int half = 0; half < 2; half++) {
            int r = row0 + wm * 32 + mf * 16 + gr + half * 8;
            if (r >= M) continue;
            int cbase = wn * 64 + ct * 2;
            if (KIND == 0 || KIND == 2) {
                __half* dst = ((KIND == 0) ? g_h : g_tmph) + (size_t)r * HID + col0 + cbase;
#pragma unroll
                for (int nf = 0; nf < 8; nf++) {
                    float x = fmaxf(acc[mf][nf][half * 2 + 0] + bb[nf][0], 0.f);
                    float y = fmaxf(acc[mf][nf][half * 2 + 1] + bb[nf][1], 0.f);
                    *(__half2*)(dst + nf * 8) = __floats2half2_rn(x, y);
                }
            } else if (KIND == 3) {
                float* dst = out + (size_t)r * D_OUTK + cbase;
#pragma unroll
                for (int nf = 0; nf < 8; nf++) {
                    float2 o;
                    o.x = fmaxf(acc[mf][nf][half * 2 + 0] + bb[nf][0], 0.f);
                    o.y = fmaxf(acc[mf][nf][half * 2 + 1] + bb[nf][1], 0.f);
                    *(float2*)(dst + nf * 8) = o;
                }
            } else {  // KIND == 1
                if (mode == 1) {
                    float* dst = out + (size_t)r * D_OUTK + cbase;
#pragma unroll
                    for (int nf = 0; nf < 8; nf++) {
                        float2 o;
                        o.x = fmaxf(acc[mf][nf][half * 2 + 0] + bb[nf][0], 0.f);
                        o.y = fmaxf(acc[mf][nf][half * 2 + 1] + bb[nf][1], 0.f);
                        *(float2*)(dst + nf * 8) = o;
                    }
                } else {
                    int sidx = (mode == 0) ? edges[2 * r] : edges[2 * r + 1];
                    float* dst = g_pooled + (size_t)sidx * HID + pcol + cbase;
#pragma unroll
                    for (int nf = 0; nf < 8; nf++) {
                        float x = fmaxf(acc[mf][nf][half * 2 + 0] + bb[nf][0], 0.f);
                        float y = fmaxf(acc[mf][nf][half * 2 + 1] + bb[nf][1], 0.f);
                        red_add_v2(dst + nf * 8, x, y);
                    }
                }
            }
        }
}

// ---------------------------------------------------------------------------
extern "C" void kernel_launch(void* const* d_in, const int* in_sizes, int n_in,
                              void* d_out, int out_size)
{
    const float* obj   = (const float*)d_in[0];
    const float* pred  = (const float*)d_in[1];
    const int*   edges = (const int*)  d_in[2];
    const float* W1 = (const float*)d_in[3];
    const float* b1 = (const float*)d_in[4];
    const float* W2 = (const float*)d_in[5];
    const float* b2 = (const float*)d_in[6];
    const float* W3 = (const float*)d_in[7];
    const float* b3 = (const float*)d_in[8];
    const float* W4 = (const float*)d_in[9];
    const float* b4 = (const float*)d_in[10];

    float* out     = (float*)d_out;
    float* out_obj = out;                           // (NOBJ, 128)
    float* out_p   = out + (size_t)NOBJ * D_OUTK;   // (NT, 128)

    cudaFuncSetAttribute(hgemm<0>, cudaFuncAttributeMaxDynamicSharedMemorySize, SMEMB);
    cudaFuncSetAttribute(hgemm<1>, cudaFuncAttributeMaxDynamicSharedMemorySize, SMEMB);
    cudaFuncSetAttribute(hgemm<2>, cudaFuncAttributeMaxDynamicSharedMemorySize, SMEMB);
    cudaFuncSetAttribute(hgemm<3>, cudaFuncAttributeMaxDynamicSharedMemorySize, SMEMB);

    zero_counts<<<(NOBJ + 255) / 256, 256>>>();
    prep_kernel<<<NB_TOTAL, 256>>>(obj, pred, edges, W1, W2, W3, W4);

    int gy_t = (NT + BM - 1) / BM;    // 1563
    int gy_o = (NOBJ + BM - 1) / BM;  // 782

    hgemm<0><<<dim3(4, gy_t), 256, SMEMB>>>(edges, b1, nullptr, NT);
    hgemm<1><<<dim3(9, gy_t), 256, SMEMB>>>(edges, b2, out_p, NT);
    normalize_h<<<(NOBJ * HID / 4 + 255) / 256, 256>>>();
    hgemm<2><<<dim3(4, gy_o), 256, SMEMB>>>(edges, b3, nullptr, NOBJ);
    hgemm<3><<<dim3(1, gy_o), 256, SMEMB>>>(edges, b4, out_obj, NOBJ);
}